// round 3
// baseline (speedup 1.0000x reference)
#include <cuda_runtime.h>

#define S_LEN 2048
#define D_INN 1024
#define NB    2
#define NH    16
#define NG    4
#define HDIM  64
#define STR   68   // padded smem row stride (floats)

// Scratch for projected Q/K/V (allocation-free rule: __device__ globals)
__device__ float g_Q[NB * NH * S_LEN * HDIM];   // [B,H,S,64]  16 MB
__device__ float g_K[NB * NG * S_LEN * HDIM];   // [B,G,S,64]   4 MB
__device__ float g_V[NB * NG * S_LEN * HDIM];   // [B,G,S,64]   4 MB

// ---------------------------------------------------------------------------
// Projection GEMM: out[b,h,s,e] = sum_d X[b,s,d] * W[h,d,e] + bias[h,e]
// Grid: (Hc, (NB*S_LEN)/64). Block 256. 64x64 tile, 4x4 per thread, k-chunk 16.
// ---------------------------------------------------------------------------
__device__ __forceinline__ void proj_body(
    const float* __restrict__ X, const float* __restrict__ W,
    const float* __restrict__ bias, float* __restrict__ out, int Hc)
{
    __shared__ float As[16 * STR];   // [k][m]
    __shared__ float Bs[16 * STR];   // [k][e]

    const int h   = blockIdx.x;
    const int m0  = blockIdx.y * 64;
    const int tid = threadIdx.x;
    const int tx  = tid & 15;        // e-quad
    const int ty  = tid >> 4;        // m-quad
    const int lm  = tid >> 2;        // A-load row (0..63)
    const int lk4 = (tid & 3) * 4;   // A-load k offset
    const int lkB = tid >> 4;        // B-load k (0..15)
    const int le4 = (tid & 15) * 4;  // B-load e offset

    float acc[4][4] = {};

    const float* Xp = X + (size_t)(m0 + lm) * D_INN + lk4;
    const float* Wp = W + ((size_t)h * D_INN + lkB) * HDIM + le4;

    for (int k0 = 0; k0 < D_INN; k0 += 16) {
        float4 xa = *(const float4*)(Xp + k0);
        float4 wb = *(const float4*)(Wp + (size_t)k0 * HDIM);
        __syncthreads();
        As[(lk4 + 0) * STR + lm] = xa.x;
        As[(lk4 + 1) * STR + lm] = xa.y;
        As[(lk4 + 2) * STR + lm] = xa.z;
        As[(lk4 + 3) * STR + lm] = xa.w;
        *(float4*)&Bs[lkB * STR + le4] = wb;
        __syncthreads();
        #pragma unroll
        for (int k = 0; k < 16; k++) {
            float4 a  = *(float4*)&As[k * STR + ty * 4];
            float4 bv = *(float4*)&Bs[k * STR + tx * 4];
            acc[0][0] = fmaf(a.x, bv.x, acc[0][0]);
            acc[0][1] = fmaf(a.x, bv.y, acc[0][1]);
            acc[0][2] = fmaf(a.x, bv.z, acc[0][2]);
            acc[0][3] = fmaf(a.x, bv.w, acc[0][3]);
            acc[1][0] = fmaf(a.y, bv.x, acc[1][0]);
            acc[1][1] = fmaf(a.y, bv.y, acc[1][1]);
            acc[1][2] = fmaf(a.y, bv.z, acc[1][2]);
            acc[1][3] = fmaf(a.y, bv.w, acc[1][3]);
            acc[2][0] = fmaf(a.z, bv.x, acc[2][0]);
            acc[2][1] = fmaf(a.z, bv.y, acc[2][1]);
            acc[2][2] = fmaf(a.z, bv.z, acc[2][2]);
            acc[2][3] = fmaf(a.z, bv.w, acc[2][3]);
            acc[3][0] = fmaf(a.w, bv.x, acc[3][0]);
            acc[3][1] = fmaf(a.w, bv.y, acc[3][1]);
            acc[3][2] = fmaf(a.w, bv.z, acc[3][2]);
            acc[3][3] = fmaf(a.w, bv.w, acc[3][3]);
        }
    }

    float4 b4 = *(const float4*)&bias[h * HDIM + tx * 4];
    #pragma unroll
    for (int i = 0; i < 4; i++) {
        int m  = m0 + ty * 4 + i;
        int bb = m / S_LEN;
        int ss = m % S_LEN;
        float4 o;
        o.x = acc[i][0] + b4.x;
        o.y = acc[i][1] + b4.y;
        o.z = acc[i][2] + b4.z;
        o.w = acc[i][3] + b4.w;
        *(float4*)&out[(((size_t)bb * Hc + h) * S_LEN + ss) * HDIM + tx * 4] = o;
    }
}

__global__ __launch_bounds__(256) void proj_q_kernel(
    const float* __restrict__ X, const float* __restrict__ W,
    const float* __restrict__ bias, float* __restrict__ out)
{
    proj_body(X, W, bias, out, NH);
}

// K and V fused: blockIdx.z selects which projection this block does.
__global__ __launch_bounds__(256) void proj_kv_kernel(
    const float* __restrict__ Xk, const float* __restrict__ Wk,
    const float* __restrict__ bk, float* __restrict__ outK,
    const float* __restrict__ Xv, const float* __restrict__ Wv,
    const float* __restrict__ bv, float* __restrict__ outV)
{
    if (blockIdx.z == 0) proj_body(Xk, Wk, bk, outK, NG);
    else                 proj_body(Xv, Wv, bv, outV, NG);
}

// ---------------------------------------------------------------------------
// Fused causal flash attention.
// Grid: (S/64, B*NH). Block 256. Thread (r, c4): q-row r = tid/4, lane c4 = tid%4.
// Owns 16 scores at k = kk*4 + c4 and 16 out dims at e = j*16 + c4*4 (+0..3).
// ---------------------------------------------------------------------------
__global__ __launch_bounds__(256) void attn_kernel(float* __restrict__ out)
{
    extern __shared__ float sm[];
    float* sQ = sm;
    float* sK = sm + 64 * STR;
    float* sV = sm + 2 * 64 * STR;
    float* sP = sm + 3 * 64 * STR;

    const int bh  = blockIdx.y;
    const int b   = bh >> 4;          // / NH
    const int h   = bh & 15;          // % NH
    const int g   = h & 3;            // % NG
    const int q0  = blockIdx.x * 64;
    const int tid = threadIdx.x;
    const int r   = tid >> 2;
    const int c4  = tid & 3;

    // Load Q tile (pre-scaled by 1/sqrt(64) = 0.125)
    #pragma unroll
    for (int t = 0; t < 4; t++) {
        int idx = tid + t * 256;
        int row = idx >> 4;
        int d4  = (idx & 15) * 4;
        float4 q = *(const float4*)&g_Q[(((size_t)(b * NH + h)) * S_LEN + q0 + row) * HDIM + d4];
        q.x *= 0.125f; q.y *= 0.125f; q.z *= 0.125f; q.w *= 0.125f;
        *(float4*)&sQ[row * STR + d4] = q;
    }

    float m_i = -1e30f, l_i = 0.f;
    float oacc[16];
    #pragma unroll
    for (int i = 0; i < 16; i++) oacc[i] = 0.f;

    const size_t kvbase = ((size_t)(b * NG + g)) * S_LEN * HDIM;
    const int ktiles = blockIdx.x + 1;   // causal: k-tiles with k0 <= q0
    const int rlim = r - c4;             // mask when kk*4 > rlim on diagonal tile

    for (int kt = 0; kt < ktiles; kt++) {
        const int k0 = kt * 64;
        __syncthreads();   // previous O-phase done reading sV/sP
        #pragma unroll
        for (int t = 0; t < 4; t++) {
            int idx = tid + t * 256;
            int row = idx >> 4;
            int d4  = (idx & 15) * 4;
            size_t go = kvbase + (size_t)(k0 + row) * HDIM + d4;
            *(float4*)&sK[row * STR + d4] = *(const float4*)&g_K[go];
            *(float4*)&sV[row * STR + d4] = *(const float4*)&g_V[go];
        }
        __syncthreads();

        // ---- scores: s[kk] = Q[r,:] . K[kk*4+c4,:]  (Q pre-scaled) ----
        float s[16];
        #pragma unroll
        for (int kk = 0; kk < 16; kk++) s[kk] = 0.f;
        #pragma unroll 4
        for (int d4 = 0; d4 < 16; d4++) {
            float4 q = *(float4*)&sQ[r * STR + d4 * 4];
            #pragma unroll
            for (int kk = 0; kk < 16; kk++) {
                float4 kv = *(float4*)&sK[(kk * 4 + c4) * STR + d4 * 4];
                s[kk] = fmaf(q.x, kv.x, s[kk]);
                s[kk] = fmaf(q.y, kv.y, s[kk]);
                s[kk] = fmaf(q.z, kv.z, s[kk]);
                s[kk] = fmaf(q.w, kv.w, s[kk]);
            }
        }

        // causal mask (diagonal tile only): k = kk*4 + c4 > r  <=>  kk*4 > r - c4
        if (k0 == q0) {
            #pragma unroll
            for (int kk = 0; kk < 16; kk++)
                if (kk * 4 > rlim) s[kk] = -1e30f;
        }

        // ---- online softmax over the 4-lane row group ----
        float tmax = s[0];
        #pragma unroll
        for (int kk = 1; kk < 16; kk++) tmax = fmaxf(tmax, s[kk]);
        tmax = fmaxf(tmax, __shfl_xor_sync(0xffffffffu, tmax, 1));
        tmax = fmaxf(tmax, __shfl_xor_sync(0xffffffffu, tmax, 2));
        float mnew = fmaxf(m_i, tmax);
        float corr = __expf(m_i - mnew);
        float lsum = 0.f;
        #pragma unroll
        for (int kk = 0; kk < 16; kk++) {
            float p = __expf(s[kk] - mnew);
            s[kk] = p;
            lsum += p;
        }
        lsum += __shfl_xor_sync(0xffffffffu, lsum, 1);
        lsum += __shfl_xor_sync(0xffffffffu, lsum, 2);
        l_i = l_i * corr + lsum;
        m_i = mnew;
        #pragma unroll
        for (int i = 0; i < 16; i++) oacc[i] *= corr;

        #pragma unroll
        for (int kk = 0; kk < 16; kk++) sP[r * STR + kk * 4 + c4] = s[kk];
        __syncthreads();

        // ---- O accumulate: oacc[e] += sum_k P[r,k] * V[k,e] ----
        const float* prow = &sP[r * STR];
        #pragma unroll 8
        for (int k = 0; k < 64; k++) {
            float p = prow[k];
            #pragma unroll
            for (int j = 0; j < 4; j++) {
                float4 v = *(float4*)&sV[k * STR + j * 16 + c4 * 4];
                oacc[j * 4 + 0] = fmaf(p, v.x, oacc[j * 4 + 0]);
                oacc[j * 4 + 1] = fmaf(p, v.y, oacc[j * 4 + 1]);
                oacc[j * 4 + 2] = fmaf(p, v.z, oacc[j * 4 + 2]);
                oacc[j * 4 + 3] = fmaf(p, v.w, oacc[j * 4 + 3]);
            }
        }
    }

    const float inv = 1.0f / l_i;
    float* op = out + ((size_t)b * S_LEN + q0 + r) * (NH * HDIM) + h * HDIM + c4 * 4;
    #pragma unroll
    for (int j = 0; j < 4; j++) {
        float4 o;
        o.x = oacc[j * 4 + 0] * inv;
        o.y = oacc[j * 4 + 1] * inv;
        o.z = oacc[j * 4 + 2] * inv;
        o.w = oacc[j * 4 + 3] * inv;
        *(float4*)&op[j * 16] = o;
    }
}

// ---------------------------------------------------------------------------
extern "C" void kernel_launch(void* const* d_in, const int* in_sizes, int n_in,
                              void* d_out, int out_size)
{
    const float* query = (const float*)d_in[0];
    const float* key   = (const float*)d_in[1];
    const float* value = (const float*)d_in[2];
    // d_in[3] = mask: deterministically tril -> causal logic used instead
    const float* Wq = (const float*)d_in[4];
    const float* bq = (const float*)d_in[5];
    const float* Wk = (const float*)d_in[6];
    const float* bk = (const float*)d_in[7];
    const float* Wv = (const float*)d_in[8];
    const float* bv = (const float*)d_in[9];
    float* out = (float*)d_out;

    float *pQ, *pK, *pV;
    cudaGetSymbolAddress((void**)&pQ, g_Q);
    cudaGetSymbolAddress((void**)&pK, g_K);
    cudaGetSymbolAddress((void**)&pV, g_V);

    const int smem_attn = 4 * 64 * STR * (int)sizeof(float);  // 69632 B
    cudaFuncSetAttribute(attn_kernel, cudaFuncAttributeMaxDynamicSharedMemorySize, smem_attn);

    dim3 gq(NH, (NB * S_LEN) / 64);
    dim3 gkv(NG, (NB * S_LEN) / 64, 2);
    proj_q_kernel<<<gq, 256>>>(query, Wq, bq, pQ);
    proj_kv_kernel<<<gkv, 256>>>(key, Wk, bk, pK, value, Wv, bv, pV);

    dim3 ga(S_LEN / 64, NB * NH);
    attn_kernel<<<ga, 256, smem_attn>>>(out);
}

// round 4
// speedup vs baseline: 3.5428x; 3.5428x over previous
#include <cuda_runtime.h>
#include <cstdint>

#define S_LEN 2048
#define D_INN 1024
#define NB    2
#define NH    16
#define NG    4
#define HDIM  64

// Scratch for projected Q/K/V (allocation-free rule: __device__ globals)
__device__ float g_Q[NB * NH * S_LEN * HDIM];   // [B,H,S,64]
__device__ float g_K[NB * NG * S_LEN * HDIM];   // [B,G,S,64]
__device__ float g_V[NB * NG * S_LEN * HDIM];   // [B,G,S,64]

// ---------------------------------------------------------------------------
// helpers
// ---------------------------------------------------------------------------
__device__ __forceinline__ uint32_t f2tf32(float f) {
    uint32_t u;
    asm("cvt.rna.tf32.f32 %0, %1;" : "=r"(u) : "f"(f));
    return u;
}

__device__ __forceinline__ void mma_tf32(float* c,
    uint32_t a0, uint32_t a1, uint32_t a2, uint32_t a3,
    uint32_t b0, uint32_t b1)
{
    asm volatile(
        "mma.sync.aligned.m16n8k8.row.col.f32.tf32.tf32.f32 "
        "{%0,%1,%2,%3}, {%4,%5,%6,%7}, {%8,%9}, {%0,%1,%2,%3};"
        : "+f"(c[0]), "+f"(c[1]), "+f"(c[2]), "+f"(c[3])
        : "r"(a0), "r"(a1), "r"(a2), "r"(a3), "r"(b0), "r"(b1));
}

// ---------------------------------------------------------------------------
// Projection GEMM (tf32 tensor cores): out[b,h,s,e] = X[b,s,:] . W[h,:,e] + bias
// Block: 128 m-rows x 64 e-cols, 256 threads (8 warps), warp w = rows w*16..+15.
// k staged 32 at a time. smem strides: sA 36 (bank: 4*gr+lc), sB 68 (4*lc+gr).
// ---------------------------------------------------------------------------
__device__ __forceinline__ void proj_body_mma(
    const float* __restrict__ X, const float* __restrict__ W,
    const float* __restrict__ bias, float* __restrict__ out, int Hc)
{
    __shared__ uint32_t sA[128 * 36];
    __shared__ uint32_t sB[32 * 68];
    __shared__ float    sBias[64];

    const int h   = blockIdx.x;
    const int m0  = blockIdx.y * 128;
    const int tid = threadIdx.x;
    const int w   = tid >> 5;
    const int lane = tid & 31;
    const int gr  = lane >> 2;
    const int lc  = lane & 3;

    if (tid < 64) sBias[tid] = bias[h * HDIM + tid];

    float acc[8][4];
    #pragma unroll
    for (int nf = 0; nf < 8; nf++)
        #pragma unroll
        for (int i = 0; i < 4; i++) acc[nf][i] = 0.f;

    const float* Xb = X + (size_t)m0 * D_INN;
    const float* Wb = W + (size_t)h * D_INN * HDIM;

    for (int k0 = 0; k0 < D_INN; k0 += 32) {
        __syncthreads();
        // A: 128 rows x 32 k  (4 float4 per thread)
        #pragma unroll
        for (int i = 0; i < 4; i++) {
            int idx = tid + i * 256;
            int row = idx >> 3;
            int kc4 = (idx & 7) * 4;
            float4 v = *(const float4*)(Xb + (size_t)row * D_INN + k0 + kc4);
            uint32_t* d = &sA[row * 36 + kc4];
            d[0] = f2tf32(v.x); d[1] = f2tf32(v.y);
            d[2] = f2tf32(v.z); d[3] = f2tf32(v.w);
        }
        // B: 32 k x 64 e  (2 float4 per thread)
        #pragma unroll
        for (int i = 0; i < 2; i++) {
            int idx = tid + i * 256;
            int kk = idx >> 4;
            int e4 = (idx & 15) * 4;
            float4 v = *(const float4*)(Wb + (size_t)(k0 + kk) * HDIM + e4);
            uint32_t* d = &sB[kk * 68 + e4];
            d[0] = f2tf32(v.x); d[1] = f2tf32(v.y);
            d[2] = f2tf32(v.z); d[3] = f2tf32(v.w);
        }
        __syncthreads();

        #pragma unroll
        for (int k8 = 0; k8 < 4; k8++) {
            int ab = (w * 16 + gr) * 36 + k8 * 8 + lc;
            uint32_t a0 = sA[ab];
            uint32_t a1 = sA[ab + 8 * 36];
            uint32_t a2 = sA[ab + 4];
            uint32_t a3 = sA[ab + 8 * 36 + 4];
            #pragma unroll
            for (int nf = 0; nf < 8; nf++) {
                int bb = (k8 * 8 + lc) * 68 + nf * 8 + gr;
                uint32_t b0 = sB[bb];
                uint32_t b1 = sB[bb + 4 * 68];
                mma_tf32(acc[nf], a0, a1, a2, a3, b0, b1);
            }
        }
    }

    // epilogue
    const int rA = m0 + w * 16 + gr;
    const int rB = rA + 8;
    const int bbA = rA / S_LEN, ssA = rA % S_LEN;
    const int bbB = rB / S_LEN, ssB = rB % S_LEN;
    float* oA = out + (((size_t)bbA * Hc + h) * S_LEN + ssA) * HDIM;
    float* oB = out + (((size_t)bbB * Hc + h) * S_LEN + ssB) * HDIM;
    #pragma unroll
    for (int nf = 0; nf < 8; nf++) {
        int e0 = nf * 8 + 2 * lc;
        float bx = sBias[e0], by = sBias[e0 + 1];
        float2 vA = make_float2(acc[nf][0] + bx, acc[nf][1] + by);
        float2 vB = make_float2(acc[nf][2] + bx, acc[nf][3] + by);
        *(float2*)(oA + e0) = vA;
        *(float2*)(oB + e0) = vB;
    }
}

__global__ __launch_bounds__(256) void proj_q_kernel(
    const float* __restrict__ X, const float* __restrict__ W,
    const float* __restrict__ bias, float* __restrict__ out)
{
    proj_body_mma(X, W, bias, out, NH);
}

__global__ __launch_bounds__(256) void proj_kv_kernel(
    const float* __restrict__ Xk, const float* __restrict__ Wk,
    const float* __restrict__ bk, float* __restrict__ outK,
    const float* __restrict__ Xv, const float* __restrict__ Wv,
    const float* __restrict__ bv, float* __restrict__ outV)
{
    if (blockIdx.z == 0) proj_body_mma(Xk, Wk, bk, outK, NG);
    else                 proj_body_mma(Xv, Wv, bv, outV, NG);
}

// ---------------------------------------------------------------------------
// Fused causal flash attention (tf32 tensor cores).
// Block: 128 q-rows, tiles of 128 k. 256 threads / 8 warps; warp w owns q-rows
// w*16..+15. QK^T: 16 n-frags; PV: 8 n-frags. Online softmax in registers,
// P routed through smem (stride 132).
// smem u32 layout: Q[128*68] K[128*68] V[128*68] P[128*132] = 172032 B.
// ---------------------------------------------------------------------------
#define OFF_K (128 * 68)
#define OFF_V (2 * 128 * 68)
#define OFF_P (3 * 128 * 68)
#define SMEM_ATTN_BYTES ((3 * 128 * 68 + 128 * 132) * 4)

__global__ __launch_bounds__(256) void attn_kernel(float* __restrict__ out)
{
    extern __shared__ uint32_t su[];
    uint32_t* sQ = su;
    uint32_t* sK = su + OFF_K;
    uint32_t* sV = su + OFF_V;
    uint32_t* sP = su + OFF_P;

    const int bh  = blockIdx.y;
    const int b   = bh >> 4;
    const int h   = bh & 15;
    const int g   = h & 3;
    const int bx  = blockIdx.x;
    const int q0  = bx * 128;
    const int tid = threadIdx.x;
    const int w   = tid >> 5;
    const int lane = tid & 31;
    const int gr  = lane >> 2;
    const int lc  = lane & 3;

    // Q scale: 1/sqrt(64) * log2(e)  (softmax done in base 2)
    const float qscale = 0.125f * 1.44269504f;

    // load Q tile (tf32)
    {
        const float* Qg = g_Q + (((size_t)(b * NH + h)) * S_LEN + q0) * HDIM;
        #pragma unroll
        for (int i = 0; i < 8; i++) {
            int idx = tid + i * 256;
            int row = idx >> 4;
            int d4  = (idx & 15) * 4;
            float4 v = *(const float4*)(Qg + (size_t)row * HDIM + d4);
            uint32_t* d = &sQ[row * 68 + d4];
            d[0] = f2tf32(v.x * qscale); d[1] = f2tf32(v.y * qscale);
            d[2] = f2tf32(v.z * qscale); d[3] = f2tf32(v.w * qscale);
        }
    }

    float mA = -1e30f, lA = 0.f, mB = -1e30f, lB = 0.f;
    float oacc[8][4];
    #pragma unroll
    for (int nf = 0; nf < 8; nf++)
        #pragma unroll
        for (int i = 0; i < 4; i++) oacc[nf][i] = 0.f;

    const float* Kg = g_K + ((size_t)(b * NG + g)) * S_LEN * HDIM;
    const float* Vg = g_V + ((size_t)(b * NG + g)) * S_LEN * HDIM;
    const int ktiles = bx + 1;

    for (int kt = 0; kt < ktiles; kt++) {
        __syncthreads();   // prior PV done with sK/sV/sP
        // load K,V tiles (tf32)
        #pragma unroll
        for (int i = 0; i < 8; i++) {
            int idx = tid + i * 256;
            int row = idx >> 4;
            int d4  = (idx & 15) * 4;
            size_t go = (size_t)(kt * 128 + row) * HDIM + d4;
            float4 kv = *(const float4*)(Kg + go);
            float4 vv = *(const float4*)(Vg + go);
            uint32_t* dk = &sK[row * 68 + d4];
            dk[0] = f2tf32(kv.x); dk[1] = f2tf32(kv.y);
            dk[2] = f2tf32(kv.z); dk[3] = f2tf32(kv.w);
            uint32_t* dv = &sV[row * 68 + d4];
            dv[0] = f2tf32(vv.x); dv[1] = f2tf32(vv.y);
            dv[2] = f2tf32(vv.z); dv[3] = f2tf32(vv.w);
        }
        __syncthreads();

        // ---- S = Q K^T (16 frags of 16x8 per warp) ----
        float sf[16][4];
        #pragma unroll
        for (int nf = 0; nf < 16; nf++)
            #pragma unroll
            for (int i = 0; i < 4; i++) sf[nf][i] = 0.f;

        #pragma unroll
        for (int k8 = 0; k8 < 8; k8++) {
            int ab = (w * 16 + gr) * 68 + k8 * 8 + lc;
            uint32_t a0 = sQ[ab];
            uint32_t a1 = sQ[ab + 8 * 68];
            uint32_t a2 = sQ[ab + 4];
            uint32_t a3 = sQ[ab + 8 * 68 + 4];
            #pragma unroll
            for (int nf = 0; nf < 16; nf++) {
                int bb = (nf * 8 + gr) * 68 + k8 * 8 + lc;
                uint32_t b0 = sK[bb];
                uint32_t b1 = sK[bb + 4];
                mma_tf32(sf[nf], a0, a1, a2, a3, b0, b1);
            }
        }

        // ---- causal mask on diagonal tile ----
        if (kt == bx) {
            int rA = w * 16 + gr, rB = rA + 8;
            #pragma unroll
            for (int nf = 0; nf < 16; nf++) {
                int c0 = nf * 8 + 2 * lc;
                if (c0     > rA) sf[nf][0] = -1e30f;
                if (c0 + 1 > rA) sf[nf][1] = -1e30f;
                if (c0     > rB) sf[nf][2] = -1e30f;
                if (c0 + 1 > rB) sf[nf][3] = -1e30f;
            }
        }

        // ---- online softmax (base-2) ----
        float tA = -1e30f, tB = -1e30f;
        #pragma unroll
        for (int nf = 0; nf < 16; nf++) {
            tA = fmaxf(tA, fmaxf(sf[nf][0], sf[nf][1]));
            tB = fmaxf(tB, fmaxf(sf[nf][2], sf[nf][3]));
        }
        tA = fmaxf(tA, __shfl_xor_sync(0xffffffffu, tA, 1));
        tA = fmaxf(tA, __shfl_xor_sync(0xffffffffu, tA, 2));
        tB = fmaxf(tB, __shfl_xor_sync(0xffffffffu, tB, 1));
        tB = fmaxf(tB, __shfl_xor_sync(0xffffffffu, tB, 2));
        float mnA = fmaxf(mA, tA);
        float mnB = fmaxf(mB, tB);
        float cA = exp2f(mA - mnA);
        float cB = exp2f(mB - mnB);
        float sumA = 0.f, sumB = 0.f;
        #pragma unroll
        for (int nf = 0; nf < 16; nf++) {
            sf[nf][0] = exp2f(sf[nf][0] - mnA);
            sf[nf][1] = exp2f(sf[nf][1] - mnA);
            sf[nf][2] = exp2f(sf[nf][2] - mnB);
            sf[nf][3] = exp2f(sf[nf][3] - mnB);
            sumA += sf[nf][0] + sf[nf][1];
            sumB += sf[nf][2] + sf[nf][3];
        }
        sumA += __shfl_xor_sync(0xffffffffu, sumA, 1);
        sumA += __shfl_xor_sync(0xffffffffu, sumA, 2);
        sumB += __shfl_xor_sync(0xffffffffu, sumB, 1);
        sumB += __shfl_xor_sync(0xffffffffu, sumB, 2);
        lA = lA * cA + sumA;  mA = mnA;
        lB = lB * cB + sumB;  mB = mnB;
        #pragma unroll
        for (int nf = 0; nf < 8; nf++) {
            oacc[nf][0] *= cA; oacc[nf][1] *= cA;
            oacc[nf][2] *= cB; oacc[nf][3] *= cB;
        }

        // ---- store P (tf32) to smem, C-layout -> A-layout via smem ----
        {
            int rowA = (w * 16 + gr) * 132;
            int rowB = rowA + 8 * 132;
            #pragma unroll
            for (int nf = 0; nf < 16; nf++) {
                int c0 = nf * 8 + 2 * lc;
                uint2 pa, pb;
                pa.x = f2tf32(sf[nf][0]); pa.y = f2tf32(sf[nf][1]);
                pb.x = f2tf32(sf[nf][2]); pb.y = f2tf32(sf[nf][3]);
                *(uint2*)&sP[rowA + c0] = pa;
                *(uint2*)&sP[rowB + c0] = pb;
            }
        }
        __syncthreads();

        // ---- O += P V  (8 frags of 16x8 per warp) ----
        #pragma unroll
        for (int k8 = 0; k8 < 16; k8++) {
            int ab = (w * 16 + gr) * 132 + k8 * 8 + lc;
            uint32_t a0 = sP[ab];
            uint32_t a1 = sP[ab + 8 * 132];
            uint32_t a2 = sP[ab + 4];
            uint32_t a3 = sP[ab + 8 * 132 + 4];
            #pragma unroll
            for (int nf = 0; nf < 8; nf++) {
                int bb = (k8 * 8 + lc) * 68 + nf * 8 + gr;
                uint32_t b0 = sV[bb];
                uint32_t b1 = sV[bb + 4 * 68];
                mma_tf32(oacc[nf], a0, a1, a2, a3, b0, b1);
            }
        }
    }

    // ---- epilogue ----
    const float iA = 1.f / lA;
    const float iB = 1.f / lB;
    const int rA = q0 + w * 16 + gr;
    const int rB = rA + 8;
    float* oA = out + ((size_t)b * S_LEN + rA) * (NH * HDIM) + h * HDIM;
    float* oB = out + ((size_t)b * S_LEN + rB) * (NH * HDIM) + h * HDIM;
    #pragma unroll
    for (int nf = 0; nf < 8; nf++) {
        int e0 = nf * 8 + 2 * lc;
        *(float2*)(oA + e0) = make_float2(oacc[nf][0] * iA, oacc[nf][1] * iA);
        *(float2*)(oB + e0) = make_float2(oacc[nf][2] * iB, oacc[nf][3] * iB);
    }
}

// ---------------------------------------------------------------------------
extern "C" void kernel_launch(void* const* d_in, const int* in_sizes, int n_in,
                              void* d_out, int out_size)
{
    const float* query = (const float*)d_in[0];
    const float* key   = (const float*)d_in[1];
    const float* value = (const float*)d_in[2];
    // d_in[3] = mask: deterministically tril -> causal logic used instead
    const float* Wq = (const float*)d_in[4];
    const float* bq = (const float*)d_in[5];
    const float* Wk = (const float*)d_in[6];
    const float* bk = (const float*)d_in[7];
    const float* Wv = (const float*)d_in[8];
    const float* bv = (const float*)d_in[9];
    float* out = (float*)d_out;

    float *pQ, *pK, *pV;
    cudaGetSymbolAddress((void**)&pQ, g_Q);
    cudaGetSymbolAddress((void**)&pK, g_K);
    cudaGetSymbolAddress((void**)&pV, g_V);

    cudaFuncSetAttribute(attn_kernel, cudaFuncAttributeMaxDynamicSharedMemorySize,
                         SMEM_ATTN_BYTES);

    dim3 gq(NH, (NB * S_LEN) / 128);
    dim3 gkv(NG, (NB * S_LEN) / 128, 2);
    proj_q_kernel<<<gq, 256>>>(query, Wq, bq, pQ);
    proj_kv_kernel<<<gkv, 256>>>(key, Wk, bk, pK, value, Wv, bv, pV);

    dim3 ga(S_LEN / 128, NB * NH);
    attn_kernel<<<ga, 256, SMEM_ATTN_BYTES>>>(out);
}

// round 5
// speedup vs baseline: 3.6743x; 1.0371x over previous
#include <cuda_runtime.h>
#include <cstdint>

#define S_LEN 2048
#define D_INN 1024
#define NB    2
#define NH    16
#define NG    4
#define HDIM  64

// Scratch for projected Q/K/V (allocation-free rule: __device__ globals)
__device__ float g_Q[NB * NH * S_LEN * HDIM];   // [B,H,S,64]
__device__ float g_K[NB * NG * S_LEN * HDIM];   // [B,G,S,64]
__device__ float g_V[NB * NG * S_LEN * HDIM];   // [B,G,S,64]

// ---------------------------------------------------------------------------
// helpers
// ---------------------------------------------------------------------------
__device__ __forceinline__ uint32_t f2tf32(float f) {
    uint32_t u;
    asm("cvt.rna.tf32.f32 %0, %1;" : "=r"(u) : "f"(f));
    return u;
}

__device__ __forceinline__ float ex2(float x) {
    float r;
    asm("ex2.approx.ftz.f32 %0, %1;" : "=f"(r) : "f"(x));
    return r;
}

__device__ __forceinline__ void mma_tf32(float* c,
    uint32_t a0, uint32_t a1, uint32_t a2, uint32_t a3,
    uint32_t b0, uint32_t b1)
{
    asm volatile(
        "mma.sync.aligned.m16n8k8.row.col.f32.tf32.tf32.f32 "
        "{%0,%1,%2,%3}, {%4,%5,%6,%7}, {%8,%9}, {%0,%1,%2,%3};"
        : "+f"(c[0]), "+f"(c[1]), "+f"(c[2]), "+f"(c[3])
        : "r"(a0), "r"(a1), "r"(a2), "r"(a3), "r"(b0), "r"(b1));
}

// ---------------------------------------------------------------------------
// Projection GEMM (tf32): out[b,h,s,e] = X[b,s,:] . W[h,:,e] + bias
// Block: 256 m-rows x 64 e, 256 threads / 8 warps; warp w owns rows w*32..+31
// (2 m-frags). k staged 32 at a time. 192 B smem per mma.
// ---------------------------------------------------------------------------
__device__ __forceinline__ void proj_body_mma(
    const float* __restrict__ X, const float* __restrict__ W,
    const float* __restrict__ bias, float* __restrict__ out, int Hc)
{
    __shared__ uint32_t sA[256 * 36];
    __shared__ uint32_t sB[32 * 68];
    __shared__ float    sBias[64];

    const int h    = blockIdx.x;
    const int m0   = blockIdx.y * 256;
    const int tid  = threadIdx.x;
    const int w    = tid >> 5;
    const int lane = tid & 31;
    const int gr   = lane >> 2;
    const int lc   = lane & 3;

    if (tid < 64) sBias[tid] = bias[h * HDIM + tid];

    float acc[2][8][4];
    #pragma unroll
    for (int mf = 0; mf < 2; mf++)
        #pragma unroll
        for (int nf = 0; nf < 8; nf++)
            #pragma unroll
            for (int i = 0; i < 4; i++) acc[mf][nf][i] = 0.f;

    const float* Xb = X + (size_t)m0 * D_INN;
    const float* Wb = W + (size_t)h * D_INN * HDIM;

    for (int k0 = 0; k0 < D_INN; k0 += 32) {
        __syncthreads();
        // A: 256 rows x 32 k  (8 float4 per thread)
        #pragma unroll
        for (int i = 0; i < 8; i++) {
            int idx = tid + i * 256;
            int row = idx >> 3;
            int kc4 = (idx & 7) * 4;
            float4 v = *(const float4*)(Xb + (size_t)row * D_INN + k0 + kc4);
            uint32_t* d = &sA[row * 36 + kc4];
            d[0] = f2tf32(v.x); d[1] = f2tf32(v.y);
            d[2] = f2tf32(v.z); d[3] = f2tf32(v.w);
        }
        // B: 32 k x 64 e  (2 float4 per thread)
        #pragma unroll
        for (int i = 0; i < 2; i++) {
            int idx = tid + i * 256;
            int kk = idx >> 4;
            int e4 = (idx & 15) * 4;
            float4 v = *(const float4*)(Wb + (size_t)(k0 + kk) * HDIM + e4);
            uint32_t* d = &sB[kk * 68 + e4];
            d[0] = f2tf32(v.x); d[1] = f2tf32(v.y);
            d[2] = f2tf32(v.z); d[3] = f2tf32(v.w);
        }
        __syncthreads();

        #pragma unroll
        for (int k8 = 0; k8 < 4; k8++) {
            uint32_t a[2][4];
            #pragma unroll
            for (int mf = 0; mf < 2; mf++) {
                int ab = (w * 32 + mf * 16 + gr) * 36 + k8 * 8 + lc;
                a[mf][0] = sA[ab];
                a[mf][1] = sA[ab + 8 * 36];
                a[mf][2] = sA[ab + 4];
                a[mf][3] = sA[ab + 8 * 36 + 4];
            }
            #pragma unroll
            for (int nf = 0; nf < 8; nf++) {
                int bb = (k8 * 8 + lc) * 68 + nf * 8 + gr;
                uint32_t b0 = sB[bb];
                uint32_t b1 = sB[bb + 4 * 68];
                mma_tf32(acc[0][nf], a[0][0], a[0][1], a[0][2], a[0][3], b0, b1);
                mma_tf32(acc[1][nf], a[1][0], a[1][1], a[1][2], a[1][3], b0, b1);
            }
        }
    }

    // epilogue
    #pragma unroll
    for (int mf = 0; mf < 2; mf++) {
        const int rA = m0 + w * 32 + mf * 16 + gr;
        const int rB = rA + 8;
        const int bbA = rA / S_LEN, ssA = rA % S_LEN;
        const int bbB = rB / S_LEN, ssB = rB % S_LEN;
        float* oA = out + (((size_t)bbA * Hc + h) * S_LEN + ssA) * HDIM;
        float* oB = out + (((size_t)bbB * Hc + h) * S_LEN + ssB) * HDIM;
        #pragma unroll
        for (int nf = 0; nf < 8; nf++) {
            int e0 = nf * 8 + 2 * lc;
            float bx = sBias[e0], by = sBias[e0 + 1];
            *(float2*)(oA + e0) = make_float2(acc[mf][nf][0] + bx, acc[mf][nf][1] + by);
            *(float2*)(oB + e0) = make_float2(acc[mf][nf][2] + bx, acc[mf][nf][3] + by);
        }
    }
}

__global__ __launch_bounds__(256) void proj_q_kernel(
    const float* __restrict__ X, const float* __restrict__ W,
    const float* __restrict__ bias, float* __restrict__ out)
{
    proj_body_mma(X, W, bias, out, NH);
}

__global__ __launch_bounds__(256) void proj_kv_kernel(
    const float* __restrict__ Xk, const float* __restrict__ Wk,
    const float* __restrict__ bk, float* __restrict__ outK,
    const float* __restrict__ Xv, const float* __restrict__ Wv,
    const float* __restrict__ bv, float* __restrict__ outV)
{
    if (blockIdx.z == 0) proj_body_mma(Xk, Wk, bk, outK, NG);
    else                 proj_body_mma(Xv, Wv, bv, outV, NG);
}

// ---------------------------------------------------------------------------
// Fused causal flash attention (tf32), Q resident in registers.
// Block: 256 q-rows, k-tiles of 64, 256 threads / 8 warps; warp w owns q-rows
// w*32..+31 (2 m-frags). smem u32: K[64*68] V[64*68] P/Qstage[256*68].
// ---------------------------------------------------------------------------
#define AOFF_V 4352
#define AOFF_P 8704
#define SMEM_ATTN_BYTES ((8704 + 17408) * 4)   // 104448

__global__ __launch_bounds__(256, 1) void attn_kernel(float* __restrict__ out)
{
    extern __shared__ uint32_t su[];
    uint32_t* sK = su;
    uint32_t* sV = su + AOFF_V;
    uint32_t* sP = su + AOFF_P;    // also Q staging before the main loop

    const int bh   = blockIdx.y;
    const int b    = bh >> 4;
    const int h    = bh & 15;
    const int g    = h & 3;
    const int jq   = (int)gridDim.x - 1 - (int)blockIdx.x;  // heavy blocks first
    const int q0   = jq * 256;
    const int tid  = threadIdx.x;
    const int w    = tid >> 5;
    const int lane = tid & 31;
    const int gr   = lane >> 2;
    const int lc   = lane & 3;

    const float qscale = 0.125f * 1.44269504f;   // 1/sqrt(64) * log2(e)

    // ---- stage Q tile into sP, then pull fragments into registers ----
    {
        const float* Qg = g_Q + (((size_t)(b * NH + h)) * S_LEN + q0) * HDIM;
        #pragma unroll
        for (int i = 0; i < 16; i++) {
            int idx = tid + i * 256;
            int row = idx >> 4;
            int d4  = (idx & 15) * 4;
            float4 v = *(const float4*)(Qg + (size_t)row * HDIM + d4);
            uint32_t* d = &sP[row * 68 + d4];
            d[0] = f2tf32(v.x * qscale); d[1] = f2tf32(v.y * qscale);
            d[2] = f2tf32(v.z * qscale); d[3] = f2tf32(v.w * qscale);
        }
    }
    __syncthreads();

    uint32_t qf[2][8][4];
    #pragma unroll
    for (int mf = 0; mf < 2; mf++)
        #pragma unroll
        for (int k8 = 0; k8 < 8; k8++) {
            int ab = (w * 32 + mf * 16 + gr) * 68 + k8 * 8 + lc;
            qf[mf][k8][0] = sP[ab];
            qf[mf][k8][1] = sP[ab + 8 * 68];
            qf[mf][k8][2] = sP[ab + 4];
            qf[mf][k8][3] = sP[ab + 8 * 68 + 4];
        }

    float mx[2][2], ls[2][2];
    #pragma unroll
    for (int mf = 0; mf < 2; mf++) { mx[mf][0] = mx[mf][1] = -1e30f; ls[mf][0] = ls[mf][1] = 0.f; }
    float oacc[2][8][4];
    #pragma unroll
    for (int mf = 0; mf < 2; mf++)
        #pragma unroll
        for (int nf = 0; nf < 8; nf++)
            #pragma unroll
            for (int i = 0; i < 4; i++) oacc[mf][nf][i] = 0.f;

    const float* Kg = g_K + ((size_t)(b * NG + g)) * S_LEN * HDIM;
    const float* Vg = g_V + ((size_t)(b * NG + g)) * S_LEN * HDIM;
    const int nkt = 4 * (jq + 1);
    const int ktm = 4 * jq;        // tiles >= ktm need causal masking

    for (int kt = 0; kt < nkt; kt++) {
        __syncthreads();   // prior PV / Q-frag readers done with sP, sK, sV
        // ---- fill K, V tiles (64 rows x 64 d) ----
        #pragma unroll
        for (int i = 0; i < 4; i++) {
            int idx = tid + i * 256;
            int row = idx >> 4;
            int d4  = (idx & 15) * 4;
            size_t go = (size_t)(kt * 64 + row) * HDIM + d4;
            float4 kv = *(const float4*)(Kg + go);
            float4 vv = *(const float4*)(Vg + go);
            uint32_t* dk = &sK[row * 68 + d4];
            dk[0] = f2tf32(kv.x); dk[1] = f2tf32(kv.y);
            dk[2] = f2tf32(kv.z); dk[3] = f2tf32(kv.w);
            uint32_t* dv = &sV[row * 68 + d4];
            dv[0] = f2tf32(vv.x); dv[1] = f2tf32(vv.y);
            dv[2] = f2tf32(vv.z); dv[3] = f2tf32(vv.w);
        }
        __syncthreads();

        // ---- S = Q K^T  (2 m-frags x 8 n-frags per warp) ----
        float sf[2][8][4];
        #pragma unroll
        for (int mf = 0; mf < 2; mf++)
            #pragma unroll
            for (int nf = 0; nf < 8; nf++)
                #pragma unroll
                for (int i = 0; i < 4; i++) sf[mf][nf][i] = 0.f;

        #pragma unroll
        for (int k8 = 0; k8 < 8; k8++) {
            #pragma unroll
            for (int nf = 0; nf < 8; nf++) {
                int bb = (nf * 8 + gr) * 68 + k8 * 8 + lc;
                uint32_t b0 = sK[bb];
                uint32_t b1 = sK[bb + 4];
                mma_tf32(sf[0][nf], qf[0][k8][0], qf[0][k8][1], qf[0][k8][2], qf[0][k8][3], b0, b1);
                mma_tf32(sf[1][nf], qf[1][k8][0], qf[1][k8][1], qf[1][k8][2], qf[1][k8][3], b0, b1);
            }
        }

        // ---- causal mask on diagonal-band tiles ----
        if (kt >= ktm) {
            int off = q0 - kt * 64;
            #pragma unroll
            for (int mf = 0; mf < 2; mf++) {
                int limA = off + w * 32 + mf * 16 + gr;
                int limB = limA + 8;
                #pragma unroll
                for (int nf = 0; nf < 8; nf++) {
                    int c0 = nf * 8 + 2 * lc;
                    if (c0     > limA) sf[mf][nf][0] = -1e30f;
                    if (c0 + 1 > limA) sf[mf][nf][1] = -1e30f;
                    if (c0     > limB) sf[mf][nf][2] = -1e30f;
                    if (c0 + 1 > limB) sf[mf][nf][3] = -1e30f;
                }
            }
        }

        // ---- online softmax (base-2) per m-frag row pair ----
        #pragma unroll
        for (int mf = 0; mf < 2; mf++) {
            float tA = -1e30f, tB = -1e30f;
            #pragma unroll
            for (int nf = 0; nf < 8; nf++) {
                tA = fmaxf(tA, fmaxf(sf[mf][nf][0], sf[mf][nf][1]));
                tB = fmaxf(tB, fmaxf(sf[mf][nf][2], sf[mf][nf][3]));
            }
            tA = fmaxf(tA, __shfl_xor_sync(0xffffffffu, tA, 1));
            tA = fmaxf(tA, __shfl_xor_sync(0xffffffffu, tA, 2));
            tB = fmaxf(tB, __shfl_xor_sync(0xffffffffu, tB, 1));
            tB = fmaxf(tB, __shfl_xor_sync(0xffffffffu, tB, 2));
            float mnA = fmaxf(mx[mf][0], tA);
            float mnB = fmaxf(mx[mf][1], tB);
            float cA = ex2(mx[mf][0] - mnA);
            float cB = ex2(mx[mf][1] - mnB);
            float sumA = 0.f, sumB = 0.f;
            #pragma unroll
            for (int nf = 0; nf < 8; nf++) {
                sf[mf][nf][0] = ex2(sf[mf][nf][0] - mnA);
                sf[mf][nf][1] = ex2(sf[mf][nf][1] - mnA);
                sf[mf][nf][2] = ex2(sf[mf][nf][2] - mnB);
                sf[mf][nf][3] = ex2(sf[mf][nf][3] - mnB);
                sumA += sf[mf][nf][0] + sf[mf][nf][1];
                sumB += sf[mf][nf][2] + sf[mf][nf][3];
            }
            sumA += __shfl_xor_sync(0xffffffffu, sumA, 1);
            sumA += __shfl_xor_sync(0xffffffffu, sumA, 2);
            sumB += __shfl_xor_sync(0xffffffffu, sumB, 1);
            sumB += __shfl_xor_sync(0xffffffffu, sumB, 2);
            ls[mf][0] = ls[mf][0] * cA + sumA;  mx[mf][0] = mnA;
            ls[mf][1] = ls[mf][1] * cB + sumB;  mx[mf][1] = mnB;
            #pragma unroll
            for (int nf = 0; nf < 8; nf++) {
                oacc[mf][nf][0] *= cA; oacc[mf][nf][1] *= cA;
                oacc[mf][nf][2] *= cB; oacc[mf][nf][3] *= cB;
            }
            // store P (tf32) to smem in A-operand layout
            int rowA = (w * 32 + mf * 16 + gr) * 68;
            int rowB = rowA + 8 * 68;
            #pragma unroll
            for (int nf = 0; nf < 8; nf++) {
                int c0 = nf * 8 + 2 * lc;
                uint2 pa, pb;
                pa.x = f2tf32(sf[mf][nf][0]); pa.y = f2tf32(sf[mf][nf][1]);
                pb.x = f2tf32(sf[mf][nf][2]); pb.y = f2tf32(sf[mf][nf][3]);
                *(uint2*)&sP[rowA + c0] = pa;
                *(uint2*)&sP[rowB + c0] = pb;
            }
        }
        __syncthreads();

        // ---- O += P V ----
        #pragma unroll
        for (int k8 = 0; k8 < 8; k8++) {
            uint32_t pa[2][4];
            #pragma unroll
            for (int mf = 0; mf < 2; mf++) {
                int ab = (w * 32 + mf * 16 + gr) * 68 + k8 * 8 + lc;
                pa[mf][0] = sP[ab];
                pa[mf][1] = sP[ab + 8 * 68];
                pa[mf][2] = sP[ab + 4];
                pa[mf][3] = sP[ab + 8 * 68 + 4];
            }
            #pragma unroll
            for (int nf = 0; nf < 8; nf++) {
                int bb = (k8 * 8 + lc) * 68 + nf * 8 + gr;
                uint32_t b0 = sV[bb];
                uint32_t b1 = sV[bb + 4 * 68];
                mma_tf32(oacc[0][nf], pa[0][0], pa[0][1], pa[0][2], pa[0][3], b0, b1);
                mma_tf32(oacc[1][nf], pa[1][0], pa[1][1], pa[1][2], pa[1][3], b0, b1);
            }
        }
    }

    // ---- epilogue ----
    #pragma unroll
    for (int mf = 0; mf < 2; mf++) {
        const float iA = 1.f / ls[mf][0];
        const float iB = 1.f / ls[mf][1];
        const int rA = q0 + w * 32 + mf * 16 + gr;
        const int rB = rA + 8;
        float* oA = out + ((size_t)b * S_LEN + rA) * (NH * HDIM) + h * HDIM;
        float* oB = out + ((size_t)b * S_LEN + rB) * (NH * HDIM) + h * HDIM;
        #pragma unroll
        for (int nf = 0; nf < 8; nf++) {
            int e0 = nf * 8 + 2 * lc;
            *(float2*)(oA + e0) = make_float2(oacc[mf][nf][0] * iA, oacc[mf][nf][1] * iA);
            *(float2*)(oB + e0) = make_float2(oacc[mf][nf][2] * iB, oacc[mf][nf][3] * iB);
        }
    }
}

// ---------------------------------------------------------------------------
extern "C" void kernel_launch(void* const* d_in, const int* in_sizes, int n_in,
                              void* d_out, int out_size)
{
    const float* query = (const float*)d_in[0];
    const float* key   = (const float*)d_in[1];
    const float* value = (const float*)d_in[2];
    // d_in[3] = mask: deterministically tril -> causal logic used instead
    const float* Wq = (const float*)d_in[4];
    const float* bq = (const float*)d_in[5];
    const float* Wk = (const float*)d_in[6];
    const float* bk = (const float*)d_in[7];
    const float* Wv = (const float*)d_in[8];
    const float* bv = (const float*)d_in[9];
    float* out = (float*)d_out;

    float *pQ, *pK, *pV;
    cudaGetSymbolAddress((void**)&pQ, g_Q);
    cudaGetSymbolAddress((void**)&pK, g_K);
    cudaGetSymbolAddress((void**)&pV, g_V);

    cudaFuncSetAttribute(attn_kernel, cudaFuncAttributeMaxDynamicSharedMemorySize,
                         SMEM_ATTN_BYTES);

    dim3 gq(NH, (NB * S_LEN) / 256);
    dim3 gkv(NG, (NB * S_LEN) / 256, 2);
    proj_q_kernel<<<gq, 256>>>(query, Wq, bq, pQ);
    proj_kv_kernel<<<gkv, 256>>>(key, Wk, bk, pK, value, Wv, bv, pV);

    dim3 ga(S_LEN / 256, NB * NH);
    attn_kernel<<<ga, 256, SMEM_ATTN_BYTES>>>(out);
}

// round 6
// speedup vs baseline: 4.6792x; 1.2735x over previous
#include <cuda_runtime.h>
#include <cstdint>

#define S_LEN 2048
#define D_INN 1024
#define NB    2
#define NH    16
#define NG    4
#define HDIM  64

// Scratch for projected Q/K/V (allocation-free rule: __device__ globals)
__device__ float g_Q[NB * NH * S_LEN * HDIM];   // [B,H,S,64]
__device__ float g_K[NB * NG * S_LEN * HDIM];   // [B,G,S,64]
__device__ float g_V[NB * NG * S_LEN * HDIM];   // [B,G,S,64]

// ---------------------------------------------------------------------------
// helpers
// ---------------------------------------------------------------------------
__device__ __forceinline__ uint32_t f2tf32(float f) {
    uint32_t u;
    asm("cvt.rna.tf32.f32 %0, %1;" : "=r"(u) : "f"(f));
    return u;
}

__device__ __forceinline__ float ex2(float x) {
    float r;
    asm("ex2.approx.ftz.f32 %0, %1;" : "=f"(r) : "f"(x));
    return r;
}

__device__ __forceinline__ void mma_tf32(float* c,
    uint32_t a0, uint32_t a1, uint32_t a2, uint32_t a3,
    uint32_t b0, uint32_t b1)
{
    asm volatile(
        "mma.sync.aligned.m16n8k8.row.col.f32.tf32.tf32.f32 "
        "{%0,%1,%2,%3}, {%4,%5,%6,%7}, {%8,%9}, {%0,%1,%2,%3};"
        : "+f"(c[0]), "+f"(c[1]), "+f"(c[2]), "+f"(c[3])
        : "r"(a0), "r"(a1), "r"(a2), "r"(a3), "r"(b0), "r"(b1));
}

__device__ __forceinline__ void cpa16(uint32_t dst, const void* src) {
    asm volatile("cp.async.cg.shared.global [%0], [%1], 16;" :: "r"(dst), "l"(src));
}
#define CP_COMMIT() asm volatile("cp.async.commit_group;")
#define CP_WAIT0()  asm volatile("cp.async.wait_group 0;")

// ---------------------------------------------------------------------------
// Projection GEMM (tf32, cp.async 2-stage pipeline):
//   out[b,h,s,e] = X[b,s,:] . W[h,:,e] + bias
// Block: 256 m x 64 e, 256 threads / 8 warps; warp w owns rows w*32..+31.
// Stages hold RAW fp32; tf32 cvt at fragment load.
// stage: A 256x36 + B 32x68 floats; stride 11392 floats; 2 stages = 91136 B.
// ---------------------------------------------------------------------------
#define PJ_STG 11392
#define SMEM_PROJ_BYTES (2 * PJ_STG * 4)

__device__ __forceinline__ void proj_body_mma(
    const float* __restrict__ X, const float* __restrict__ W,
    const float* __restrict__ bias, float* __restrict__ out, int Hc)
{
    extern __shared__ float dsm[];
    __shared__ float sBias[64];

    const int h    = blockIdx.x;
    const int m0   = blockIdx.y * 256;
    const int tid  = threadIdx.x;
    const int w    = tid >> 5;
    const int lane = tid & 31;
    const int gr   = lane >> 2;
    const int lc   = lane & 3;

    if (tid < 64) sBias[tid] = bias[h * HDIM + tid];

    const float* Xb = X + (size_t)m0 * D_INN;
    const float* Wb = W + (size_t)h * D_INN * HDIM;

    // per-thread fill coordinates
    const int arow = tid >> 3;            // +64 per i
    const int akc  = (tid & 7) * 4;
    const int bkk  = tid >> 4;            // +16 per i
    const int be4  = (tid & 15) * 4;

    // stage base smem addresses (u32 byte addresses for cp.async)
    uint32_t aBase[2], bBase[2];
    #pragma unroll
    for (int s = 0; s < 2; s++) {
        aBase[s] = (uint32_t)__cvta_generic_to_shared(dsm + s * PJ_STG);
        bBase[s] = aBase[s] + 9216u * 4u;
    }

    // issue one k-chunk into stage st
    auto issue = [&](int st, int k0) {
        #pragma unroll
        for (int i = 0; i < 8; i++) {
            int row = arow + i * 32;
            cpa16(aBase[st] + (uint32_t)(row * 36 + akc) * 4u,
                  Xb + (size_t)row * D_INN + k0 + akc);
        }
        #pragma unroll
        for (int i = 0; i < 2; i++) {
            int kk = bkk + i * 16;
            cpa16(bBase[st] + (uint32_t)(kk * 68 + be4) * 4u,
                  Wb + (size_t)(k0 + kk) * HDIM + be4);
        }
        CP_COMMIT();
    };

    float acc[2][8][4];
    #pragma unroll
    for (int mf = 0; mf < 2; mf++)
        #pragma unroll
        for (int nf = 0; nf < 8; nf++)
            #pragma unroll
            for (int i = 0; i < 4; i++) acc[mf][nf][i] = 0.f;

    issue(0, 0);

    for (int c = 0; c < 32; c++) {
        const int s = c & 1;
        CP_WAIT0();
        __syncthreads();
        if (c + 1 < 32) issue(s ^ 1, (c + 1) * 32);

        const float* sA = dsm + s * PJ_STG;
        const float* sB = sA + 9216;

        #pragma unroll
        for (int k8 = 0; k8 < 4; k8++) {
            uint32_t a[2][4];
            #pragma unroll
            for (int mf = 0; mf < 2; mf++) {
                int ab = (w * 32 + mf * 16 + gr) * 36 + k8 * 8 + lc;
                a[mf][0] = f2tf32(sA[ab]);
                a[mf][1] = f2tf32(sA[ab + 8 * 36]);
                a[mf][2] = f2tf32(sA[ab + 4]);
                a[mf][3] = f2tf32(sA[ab + 8 * 36 + 4]);
            }
            #pragma unroll
            for (int nf = 0; nf < 8; nf++) {
                int bb = (k8 * 8 + lc) * 68 + nf * 8 + gr;
                uint32_t b0 = f2tf32(sB[bb]);
                uint32_t b1 = f2tf32(sB[bb + 4 * 68]);
                mma_tf32(acc[0][nf], a[0][0], a[0][1], a[0][2], a[0][3], b0, b1);
                mma_tf32(acc[1][nf], a[1][0], a[1][1], a[1][2], a[1][3], b0, b1);
            }
        }
        // no trailing sync needed: stage s is next written at iter c+2,
        // whose issue happens after iter c+1's barrier.
    }

    // epilogue
    #pragma unroll
    for (int mf = 0; mf < 2; mf++) {
        const int rA = m0 + w * 32 + mf * 16 + gr;
        const int rB = rA + 8;
        const int bbA = rA / S_LEN, ssA = rA % S_LEN;
        const int bbB = rB / S_LEN, ssB = rB % S_LEN;
        float* oA = out + (((size_t)bbA * Hc + h) * S_LEN + ssA) * HDIM;
        float* oB = out + (((size_t)bbB * Hc + h) * S_LEN + ssB) * HDIM;
        #pragma unroll
        for (int nf = 0; nf < 8; nf++) {
            int e0 = nf * 8 + 2 * lc;
            float bx = sBias[e0], by = sBias[e0 + 1];
            *(float2*)(oA + e0) = make_float2(acc[mf][nf][0] + bx, acc[mf][nf][1] + by);
            *(float2*)(oB + e0) = make_float2(acc[mf][nf][2] + bx, acc[mf][nf][3] + by);
        }
    }
}

__global__ __launch_bounds__(256, 2) void proj_q_kernel(
    const float* __restrict__ X, const float* __restrict__ W,
    const float* __restrict__ bias, float* __restrict__ out)
{
    proj_body_mma(X, W, bias, out, NH);
}

__global__ __launch_bounds__(256, 2) void proj_kv_kernel(
    const float* __restrict__ Xk, const float* __restrict__ Wk,
    const float* __restrict__ bk, float* __restrict__ outK,
    const float* __restrict__ Xv, const float* __restrict__ Wv,
    const float* __restrict__ bv, float* __restrict__ outV)
{
    if (blockIdx.z == 0) proj_body_mma(Xk, Wk, bk, outK, NG);
    else                 proj_body_mma(Xv, Wv, bv, outV, NG);
}

// ---------------------------------------------------------------------------
// Fused causal flash attention (tf32, Q in registers, cp.async 2-stage K/V).
// Block: 256 q-rows, k-tiles of 64, 256 threads / 8 warps.
// smem floats: K0[4352] K1[4352] V0[4352] V1[4352] P[17408] = 139264 B.
// ---------------------------------------------------------------------------
#define AT_KV   4352
#define AT_POFF 17408
#define SMEM_ATTN_BYTES ((4 * AT_KV + 17408) * 4)

__global__ __launch_bounds__(256, 1) void attn_kernel(float* __restrict__ out)
{
    extern __shared__ float su[];
    uint32_t* sP = (uint32_t*)(su + AT_POFF);   // tf32 bits; also Q staging

    const int bh   = blockIdx.y;
    const int b    = bh >> 4;
    const int h    = bh & 15;
    const int g    = h & 3;
    const int jq   = (int)gridDim.x - 1 - (int)blockIdx.x;  // heavy blocks first
    const int q0   = jq * 256;
    const int tid  = threadIdx.x;
    const int w    = tid >> 5;
    const int lane = tid & 31;
    const int gr   = lane >> 2;
    const int lc   = lane & 3;

    const float qscale = 0.125f * 1.44269504f;   // 1/sqrt(64) * log2(e)

    const float* Kg = g_K + ((size_t)(b * NG + g)) * S_LEN * HDIM;
    const float* Vg = g_V + ((size_t)(b * NG + g)) * S_LEN * HDIM;

    // fill coordinates
    const int frow = tid >> 4;            // +16 per i
    const int fd4  = (tid & 15) * 4;
    uint32_t kBase[2], vBase[2];
    #pragma unroll
    for (int s = 0; s < 2; s++) {
        kBase[s] = (uint32_t)__cvta_generic_to_shared(su + s * AT_KV);
        vBase[s] = (uint32_t)__cvta_generic_to_shared(su + (2 + s) * AT_KV);
    }

    auto issue = [&](int st, int kt) {
        #pragma unroll
        for (int i = 0; i < 4; i++) {
            int row = frow + i * 16;
            uint32_t off = (uint32_t)(row * 68 + fd4) * 4u;
            size_t go = (size_t)(kt * 64 + row) * HDIM + fd4;
            cpa16(kBase[st] + off, Kg + go);
            cpa16(vBase[st] + off, Vg + go);
        }
        CP_COMMIT();
    };

    // ---- stage Q tile into sP, then pull fragments into registers ----
    {
        const float* Qg = g_Q + (((size_t)(b * NH + h)) * S_LEN + q0) * HDIM;
        #pragma unroll
        for (int i = 0; i < 16; i++) {
            int idx = tid + i * 256;
            int row = idx >> 4;
            int d4  = (idx & 15) * 4;
            float4 v = *(const float4*)(Qg + (size_t)row * HDIM + d4);
            uint32_t* d = &sP[row * 68 + d4];
            d[0] = f2tf32(v.x * qscale); d[1] = f2tf32(v.y * qscale);
            d[2] = f2tf32(v.z * qscale); d[3] = f2tf32(v.w * qscale);
        }
    }
    __syncthreads();

    uint32_t qf[2][8][4];
    #pragma unroll
    for (int mf = 0; mf < 2; mf++)
        #pragma unroll
        for (int k8 = 0; k8 < 8; k8++) {
            int ab = (w * 32 + mf * 16 + gr) * 68 + k8 * 8 + lc;
            qf[mf][k8][0] = sP[ab];
            qf[mf][k8][1] = sP[ab + 8 * 68];
            qf[mf][k8][2] = sP[ab + 4];
            qf[mf][k8][3] = sP[ab + 8 * 68 + 4];
        }

    float mx[2][2], ls[2][2];
    #pragma unroll
    for (int mf = 0; mf < 2; mf++) { mx[mf][0] = mx[mf][1] = -1e30f; ls[mf][0] = ls[mf][1] = 0.f; }
    float oacc[2][8][4];
    #pragma unroll
    for (int mf = 0; mf < 2; mf++)
        #pragma unroll
        for (int nf = 0; nf < 8; nf++)
            #pragma unroll
            for (int i = 0; i < 4; i++) oacc[mf][nf][i] = 0.f;

    const int nkt = 4 * (jq + 1);
    const int ktm = 4 * jq;        // tiles >= ktm need causal masking

    issue(0, 0);

    for (int kt = 0; kt < nkt; kt++) {
        const int s = kt & 1;
        CP_WAIT0();
        __syncthreads();                       // (A) tile kt ready; prior PV done
        if (kt + 1 < nkt) issue(s ^ 1, kt + 1);

        const float* Ks = su + s * AT_KV;
        const float* Vs = su + (2 + s) * AT_KV;

        // ---- S = Q K^T ----
        float sf[2][8][4];
        #pragma unroll
        for (int mf = 0; mf < 2; mf++)
            #pragma unroll
            for (int nf = 0; nf < 8; nf++)
                #pragma unroll
                for (int i = 0; i < 4; i++) sf[mf][nf][i] = 0.f;

        #pragma unroll
        for (int k8 = 0; k8 < 8; k8++) {
            #pragma unroll
            for (int nf = 0; nf < 8; nf++) {
                int bb = (nf * 8 + gr) * 68 + k8 * 8 + lc;
                uint32_t b0 = f2tf32(Ks[bb]);
                uint32_t b1 = f2tf32(Ks[bb + 4]);
                mma_tf32(sf[0][nf], qf[0][k8][0], qf[0][k8][1], qf[0][k8][2], qf[0][k8][3], b0, b1);
                mma_tf32(sf[1][nf], qf[1][k8][0], qf[1][k8][1], qf[1][k8][2], qf[1][k8][3], b0, b1);
            }
        }

        // ---- causal mask on diagonal-band tiles ----
        if (kt >= ktm) {
            int off = q0 - kt * 64;
            #pragma unroll
            for (int mf = 0; mf < 2; mf++) {
                int limA = off + w * 32 + mf * 16 + gr;
                int limB = limA + 8;
                #pragma unroll
                for (int nf = 0; nf < 8; nf++) {
                    int c0 = nf * 8 + 2 * lc;
                    if (c0     > limA) sf[mf][nf][0] = -1e30f;
                    if (c0 + 1 > limA) sf[mf][nf][1] = -1e30f;
                    if (c0     > limB) sf[mf][nf][2] = -1e30f;
                    if (c0 + 1 > limB) sf[mf][nf][3] = -1e30f;
                }
            }
        }

        // ---- online softmax (base-2) ----
        #pragma unroll
        for (int mf = 0; mf < 2; mf++) {
            float tA = -1e30f, tB = -1e30f;
            #pragma unroll
            for (int nf = 0; nf < 8; nf++) {
                tA = fmaxf(tA, fmaxf(sf[mf][nf][0], sf[mf][nf][1]));
                tB = fmaxf(tB, fmaxf(sf[mf][nf][2], sf[mf][nf][3]));
            }
            tA = fmaxf(tA, __shfl_xor_sync(0xffffffffu, tA, 1));
            tA = fmaxf(tA, __shfl_xor_sync(0xffffffffu, tA, 2));
            tB = fmaxf(tB, __shfl_xor_sync(0xffffffffu, tB, 1));
            tB = fmaxf(tB, __shfl_xor_sync(0xffffffffu, tB, 2));
            float mnA = fmaxf(mx[mf][0], tA);
            float mnB = fmaxf(mx[mf][1], tB);
            float cA = ex2(mx[mf][0] - mnA);
            float cB = ex2(mx[mf][1] - mnB);
            float sumA = 0.f, sumB = 0.f;
            #pragma unroll
            for (int nf = 0; nf < 8; nf++) {
                sf[mf][nf][0] = ex2(sf[mf][nf][0] - mnA);
                sf[mf][nf][1] = ex2(sf[mf][nf][1] - mnA);
                sf[mf][nf][2] = ex2(sf[mf][nf][2] - mnB);
                sf[mf][nf][3] = ex2(sf[mf][nf][3] - mnB);
                sumA += sf[mf][nf][0] + sf[mf][nf][1];
                sumB += sf[mf][nf][2] + sf[mf][nf][3];
            }
            sumA += __shfl_xor_sync(0xffffffffu, sumA, 1);
            sumA += __shfl_xor_sync(0xffffffffu, sumA, 2);
            sumB += __shfl_xor_sync(0xffffffffu, sumB, 1);
            sumB += __shfl_xor_sync(0xffffffffu, sumB, 2);
            ls[mf][0] = ls[mf][0] * cA + sumA;  mx[mf][0] = mnA;
            ls[mf][1] = ls[mf][1] * cB + sumB;  mx[mf][1] = mnB;
            #pragma unroll
            for (int nf = 0; nf < 8; nf++) {
                oacc[mf][nf][0] *= cA; oacc[mf][nf][1] *= cA;
                oacc[mf][nf][2] *= cB; oacc[mf][nf][3] *= cB;
            }
            // store P (tf32 bits) in A-operand layout
            int rowA = (w * 32 + mf * 16 + gr) * 68;
            int rowB = rowA + 8 * 68;
            #pragma unroll
            for (int nf = 0; nf < 8; nf++) {
                int c0 = nf * 8 + 2 * lc;
                uint2 pa, pb;
                pa.x = f2tf32(sf[mf][nf][0]); pa.y = f2tf32(sf[mf][nf][1]);
                pb.x = f2tf32(sf[mf][nf][2]); pb.y = f2tf32(sf[mf][nf][3]);
                *(uint2*)&sP[rowA + c0] = pa;
                *(uint2*)&sP[rowB + c0] = pb;
            }
        }
        __syncthreads();                       // (B) P visible; K reads done

        // ---- O += P V ----
        #pragma unroll
        for (int k8 = 0; k8 < 8; k8++) {
            uint32_t pa[2][4];
            #pragma unroll
            for (int mf = 0; mf < 2; mf++) {
                int ab = (w * 32 + mf * 16 + gr) * 68 + k8 * 8 + lc;
                pa[mf][0] = sP[ab];
                pa[mf][1] = sP[ab + 8 * 68];
                pa[mf][2] = sP[ab + 4];
                pa[mf][3] = sP[ab + 8 * 68 + 4];
            }
            #pragma unroll
            for (int nf = 0; nf < 8; nf++) {
                int bb = (k8 * 8 + lc) * 68 + nf * 8 + gr;
                uint32_t b0 = f2tf32(Vs[bb]);
                uint32_t b1 = f2tf32(Vs[bb + 4 * 68]);
                mma_tf32(oacc[0][nf], pa[0][0], pa[0][1], pa[0][2], pa[0][3], b0, b1);
                mma_tf32(oacc[1][nf], pa[1][0], pa[1][1], pa[1][2], pa[1][3], b0, b1);
            }
        }
    }

    // ---- epilogue ----
    #pragma unroll
    for (int mf = 0; mf < 2; mf++) {
        const float iA = 1.f / ls[mf][0];
        const float iB = 1.f / ls[mf][1];
        const int rA = q0 + w * 32 + mf * 16 + gr;
        const int rB = rA + 8;
        float* oA = out + ((size_t)b * S_LEN + rA) * (NH * HDIM) + h * HDIM;
        float* oB = out + ((size_t)b * S_LEN + rB) * (NH * HDIM) + h * HDIM;
        #pragma unroll
        for (int nf = 0; nf < 8; nf++) {
            int e0 = nf * 8 + 2 * lc;
            *(float2*)(oA + e0) = make_float2(oacc[mf][nf][0] * iA, oacc[mf][nf][1] * iA);
            *(float2*)(oB + e0) = make_float2(oacc[mf][nf][2] * iB, oacc[mf][nf][3] * iB);
        }
    }
}

// ---------------------------------------------------------------------------
extern "C" void kernel_launch(void* const* d_in, const int* in_sizes, int n_in,
                              void* d_out, int out_size)
{
    const float* query = (const float*)d_in[0];
    const float* key   = (const float*)d_in[1];
    const float* value = (const float*)d_in[2];
    // d_in[3] = mask: deterministically tril -> causal logic used instead
    const float* Wq = (const float*)d_in[4];
    const float* bq = (const float*)d_in[5];
    const float* Wk = (const float*)d_in[6];
    const float* bk = (const float*)d_in[7];
    const float* Wv = (const float*)d_in[8];
    const float* bv = (const float*)d_in[9];
    float* out = (float*)d_out;

    float *pQ, *pK, *pV;
    cudaGetSymbolAddress((void**)&pQ, g_Q);
    cudaGetSymbolAddress((void**)&pK, g_K);
    cudaGetSymbolAddress((void**)&pV, g_V);

    cudaFuncSetAttribute(proj_q_kernel,  cudaFuncAttributeMaxDynamicSharedMemorySize, SMEM_PROJ_BYTES);
    cudaFuncSetAttribute(proj_kv_kernel, cudaFuncAttributeMaxDynamicSharedMemorySize, SMEM_PROJ_BYTES);
    cudaFuncSetAttribute(attn_kernel,    cudaFuncAttributeMaxDynamicSharedMemorySize, SMEM_ATTN_BYTES);

    dim3 gq(NH, (NB * S_LEN) / 256);
    dim3 gkv(NG, (NB * S_LEN) / 256, 2);
    proj_q_kernel<<<gq, 256, SMEM_PROJ_BYTES>>>(query, Wq, bq, pQ);
    proj_kv_kernel<<<gkv, 256, SMEM_PROJ_BYTES>>>(key, Wk, bk, pK, value, Wv, bv, pV);

    dim3 ga(S_LEN / 256, NB * NH);
    attn_kernel<<<ga, 256, SMEM_ATTN_BYTES>>>(out);
}

// round 7
// speedup vs baseline: 5.6585x; 1.2093x over previous
#include <cuda_runtime.h>
#include <cstdint>

#define S_LEN 2048
#define D_INN 1024
#define NB    2
#define NH    16
#define NG    4
#define HDIM  64

// Scratch: projected Q/K/V stored as TF32 BITS (Q pre-scaled by 0.125*log2e)
__device__ float g_Q[NB * NH * S_LEN * HDIM];   // [B,H,S,64]
__device__ float g_K[NB * NG * S_LEN * HDIM];   // [B,G,S,64]
__device__ float g_V[NB * NG * S_LEN * HDIM];   // [B,G,S,64]

// ---------------------------------------------------------------------------
// helpers
// ---------------------------------------------------------------------------
__device__ __forceinline__ uint32_t f2tf32(float f) {
    uint32_t u;
    asm("cvt.rna.tf32.f32 %0, %1;" : "=r"(u) : "f"(f));
    return u;
}

__device__ __forceinline__ float ex2(float x) {
    float r;
    asm("ex2.approx.ftz.f32 %0, %1;" : "=f"(r) : "f"(x));
    return r;
}

__device__ __forceinline__ void mma_tf32(float* c,
    uint32_t a0, uint32_t a1, uint32_t a2, uint32_t a3,
    uint32_t b0, uint32_t b1)
{
    asm volatile(
        "mma.sync.aligned.m16n8k8.row.col.f32.tf32.tf32.f32 "
        "{%0,%1,%2,%3}, {%4,%5,%6,%7}, {%8,%9}, {%0,%1,%2,%3};"
        : "+f"(c[0]), "+f"(c[1]), "+f"(c[2]), "+f"(c[3])
        : "r"(a0), "r"(a1), "r"(a2), "r"(a3), "r"(b0), "r"(b1));
}

__device__ __forceinline__ void cpa16(uint32_t dst, const void* src) {
    asm volatile("cp.async.cg.shared.global [%0], [%1], 16;" :: "r"(dst), "l"(src));
}
#define CP_COMMIT() asm volatile("cp.async.commit_group;")
#define CP_WAIT0()  asm volatile("cp.async.wait_group 0;")

#define QSCALE (0.125f * 1.44269504f)   // 1/sqrt(64) * log2(e)

// ---------------------------------------------------------------------------
// Projection GEMM (tf32, cp.async 2-stage). Epilogue stores TF32 BITS.
// Block: 256 m x 64 e, 256 threads / 8 warps.
// stage: A 256x36 + B 32x68 floats; stride 11392; 2 stages = 91136 B.
// ---------------------------------------------------------------------------
#define PJ_STG 11392
#define SMEM_PROJ_BYTES (2 * PJ_STG * 4)

__device__ __forceinline__ void proj_body_mma(
    const float* __restrict__ X, const float* __restrict__ W,
    const float* __restrict__ bias, float* __restrict__ out,
    int Hc, int h, float oscale)
{
    extern __shared__ float dsm[];
    __shared__ float sBias[64];

    const int m0   = blockIdx.y * 256;
    const int tid  = threadIdx.x;
    const int w    = tid >> 5;
    const int lane = tid & 31;
    const int gr   = lane >> 2;
    const int lc   = lane & 3;

    if (tid < 64) sBias[tid] = bias[h * HDIM + tid];

    const float* Xb = X + (size_t)m0 * D_INN;
    const float* Wb = W + (size_t)h * D_INN * HDIM;

    const int arow = tid >> 3;
    const int akc  = (tid & 7) * 4;
    const int bkk  = tid >> 4;
    const int be4  = (tid & 15) * 4;

    uint32_t aBase[2], bBase[2];
    #pragma unroll
    for (int s = 0; s < 2; s++) {
        aBase[s] = (uint32_t)__cvta_generic_to_shared(dsm + s * PJ_STG);
        bBase[s] = aBase[s] + 9216u * 4u;
    }

    auto issue = [&](int st, int k0) {
        #pragma unroll
        for (int i = 0; i < 8; i++) {
            int row = arow + i * 32;
            cpa16(aBase[st] + (uint32_t)(row * 36 + akc) * 4u,
                  Xb + (size_t)row * D_INN + k0 + akc);
        }
        #pragma unroll
        for (int i = 0; i < 2; i++) {
            int kk = bkk + i * 16;
            cpa16(bBase[st] + (uint32_t)(kk * 68 + be4) * 4u,
                  Wb + (size_t)(k0 + kk) * HDIM + be4);
        }
        CP_COMMIT();
    };

    float acc[2][8][4];
    #pragma unroll
    for (int mf = 0; mf < 2; mf++)
        #pragma unroll
        for (int nf = 0; nf < 8; nf++)
            #pragma unroll
            for (int i = 0; i < 4; i++) acc[mf][nf][i] = 0.f;

    issue(0, 0);

    for (int c = 0; c < 32; c++) {
        const int s = c & 1;
        CP_WAIT0();
        __syncthreads();
        if (c + 1 < 32) issue(s ^ 1, (c + 1) * 32);

        const float* sA = dsm + s * PJ_STG;
        const float* sB = sA + 9216;

        #pragma unroll
        for (int k8 = 0; k8 < 4; k8++) {
            uint32_t a[2][4];
            #pragma unroll
            for (int mf = 0; mf < 2; mf++) {
                int ab = (w * 32 + mf * 16 + gr) * 36 + k8 * 8 + lc;
                a[mf][0] = f2tf32(sA[ab]);
                a[mf][1] = f2tf32(sA[ab + 8 * 36]);
                a[mf][2] = f2tf32(sA[ab + 4]);
                a[mf][3] = f2tf32(sA[ab + 8 * 36 + 4]);
            }
            #pragma unroll
            for (int nf = 0; nf < 8; nf++) {
                int bb = (k8 * 8 + lc) * 68 + nf * 8 + gr;
                uint32_t b0 = f2tf32(sB[bb]);
                uint32_t b1 = f2tf32(sB[bb + 4 * 68]);
                mma_tf32(acc[0][nf], a[0][0], a[0][1], a[0][2], a[0][3], b0, b1);
                mma_tf32(acc[1][nf], a[1][0], a[1][1], a[1][2], a[1][3], b0, b1);
            }
        }
    }

    // epilogue: add bias, apply scale, convert to tf32 bits, store
    #pragma unroll
    for (int mf = 0; mf < 2; mf++) {
        const int rA = m0 + w * 32 + mf * 16 + gr;
        const int rB = rA + 8;
        const int bbA = rA / S_LEN, ssA = rA % S_LEN;
        const int bbB = rB / S_LEN, ssB = rB % S_LEN;
        float* oA = out + (((size_t)bbA * Hc + h) * S_LEN + ssA) * HDIM;
        float* oB = out + (((size_t)bbB * Hc + h) * S_LEN + ssB) * HDIM;
        #pragma unroll
        for (int nf = 0; nf < 8; nf++) {
            int e0 = nf * 8 + 2 * lc;
            float bx = sBias[e0], by = sBias[e0 + 1];
            float2 vA, vB;
            vA.x = __uint_as_float(f2tf32((acc[mf][nf][0] + bx) * oscale));
            vA.y = __uint_as_float(f2tf32((acc[mf][nf][1] + by) * oscale));
            vB.x = __uint_as_float(f2tf32((acc[mf][nf][2] + bx) * oscale));
            vB.y = __uint_as_float(f2tf32((acc[mf][nf][3] + by) * oscale));
            *(float2*)(oA + e0) = vA;
            *(float2*)(oB + e0) = vB;
        }
    }
}

// One launch for all projections: unit u = blockIdx.x
// u in [0,16): Q head u | [16,20): K group u-16 | [20,24): V group u-20
__global__ __launch_bounds__(256, 2) void proj_all_kernel(
    const float* __restrict__ q,  const float* __restrict__ k,
    const float* __restrict__ v,
    const float* __restrict__ Wq, const float* __restrict__ bq, float* outQ,
    const float* __restrict__ Wk, const float* __restrict__ bk, float* outK,
    const float* __restrict__ Wv, const float* __restrict__ bv, float* outV)
{
    const int u = blockIdx.x;
    if (u < 16)      proj_body_mma(q, Wq, bq, outQ, NH, u,      QSCALE);
    else if (u < 20) proj_body_mma(k, Wk, bk, outK, NG, u - 16, 1.0f);
    else             proj_body_mma(v, Wv, bv, outV, NG, u - 20, 1.0f);
}

// ---------------------------------------------------------------------------
// Fused causal flash attention. Inputs already tf32 bits (Q pre-scaled).
// Block: 128 q-rows, 128 threads / 4 warps; warp w owns q-rows w*32..+31.
// k-tiles of 64, cp.async 2-stage. 2 blocks/SM.
// smem floats: K0 K1 V0 V1 [4*4352] + P/Qstage [128*68] = 104448 B.
// ---------------------------------------------------------------------------
#define AT_KV   4352
#define AT_POFF 17408
#define SMEM_ATTN_BYTES ((4 * AT_KV + 128 * 68) * 4)

__global__ __launch_bounds__(128, 2) void attn_kernel(float* __restrict__ out)
{
    extern __shared__ float su[];
    uint32_t* sP = (uint32_t*)(su + AT_POFF);   // P buffer; also Q staging

    const int bh   = blockIdx.y;
    const int b    = bh >> 4;
    const int h    = bh & 15;
    const int g    = h & 3;
    const int jq   = (int)gridDim.x - 1 - (int)blockIdx.x;  // heavy blocks first
    const int q0   = jq * 128;
    const int tid  = threadIdx.x;
    const int w    = tid >> 5;
    const int lane = tid & 31;
    const int gr   = lane >> 2;
    const int lc   = lane & 3;

    const float* Kg = g_K + ((size_t)(b * NG + g)) * S_LEN * HDIM;
    const float* Vg = g_V + ((size_t)(b * NG + g)) * S_LEN * HDIM;

    const int frow = tid >> 4;            // +8 per i (128 thr)
    const int fd4  = (tid & 15) * 4;
    uint32_t kBase[2], vBase[2];
    #pragma unroll
    for (int s = 0; s < 2; s++) {
        kBase[s] = (uint32_t)__cvta_generic_to_shared(su + s * AT_KV);
        vBase[s] = (uint32_t)__cvta_generic_to_shared(su + (2 + s) * AT_KV);
    }

    auto issue = [&](int st, int kt) {
        #pragma unroll
        for (int i = 0; i < 8; i++) {
            int row = frow + i * 8;
            uint32_t off = (uint32_t)(row * 68 + fd4) * 4u;
            size_t go = (size_t)(kt * 64 + row) * HDIM + fd4;
            cpa16(kBase[st] + off, Kg + go);
            cpa16(vBase[st] + off, Vg + go);
        }
        CP_COMMIT();
    };

    // ---- stage Q tile (tf32 bits, pre-scaled) via cp.async, read fragments ----
    {
        const float* Qg = g_Q + (((size_t)(b * NH + h)) * S_LEN + q0) * HDIM;
        uint32_t pBase = (uint32_t)__cvta_generic_to_shared(su + AT_POFF);
        #pragma unroll
        for (int i = 0; i < 16; i++) {
            int idx = tid + i * 128;
            int row = idx >> 4;
            int d4  = (idx & 15) * 4;
            cpa16(pBase + (uint32_t)(row * 68 + d4) * 4u,
                  Qg + (size_t)row * HDIM + d4);
        }
        CP_COMMIT();
    }
    issue(0, 0);
    CP_WAIT0();
    __syncthreads();

    uint32_t qf[2][8][4];
    #pragma unroll
    for (int mf = 0; mf < 2; mf++)
        #pragma unroll
        for (int k8 = 0; k8 < 8; k8++) {
            int ab = (w * 32 + mf * 16 + gr) * 68 + k8 * 8 + lc;
            qf[mf][k8][0] = sP[ab];
            qf[mf][k8][1] = sP[ab + 8 * 68];
            qf[mf][k8][2] = sP[ab + 4];
            qf[mf][k8][3] = sP[ab + 8 * 68 + 4];
        }

    float mx[2][2], ls[2][2];
    #pragma unroll
    for (int mf = 0; mf < 2; mf++) { mx[mf][0] = mx[mf][1] = -1e30f; ls[mf][0] = ls[mf][1] = 0.f; }
    float oacc[2][8][4];
    #pragma unroll
    for (int mf = 0; mf < 2; mf++)
        #pragma unroll
        for (int nf = 0; nf < 8; nf++)
            #pragma unroll
            for (int i = 0; i < 4; i++) oacc[mf][nf][i] = 0.f;

    const int nkt = 2 * (jq + 1);
    const int ktm = 2 * jq;        // tiles >= ktm need causal masking

    for (int kt = 0; kt < nkt; kt++) {
        const int s = kt & 1;
        CP_WAIT0();
        __syncthreads();                       // (A) tile kt ready; prior PV + qf reads done
        if (kt + 1 < nkt) issue(s ^ 1, kt + 1);

        const uint32_t* Ks = (const uint32_t*)(su + s * AT_KV);
        const uint32_t* Vs = (const uint32_t*)(su + (2 + s) * AT_KV);

        // ---- S = Q K^T ----
        float sf[2][8][4];
        #pragma unroll
        for (int mf = 0; mf < 2; mf++)
            #pragma unroll
            for (int nf = 0; nf < 8; nf++)
                #pragma unroll
                for (int i = 0; i < 4; i++) sf[mf][nf][i] = 0.f;

        #pragma unroll
        for (int k8 = 0; k8 < 8; k8++) {
            #pragma unroll
            for (int nf = 0; nf < 8; nf++) {
                int bb = (nf * 8 + gr) * 68 + k8 * 8 + lc;
                uint32_t b0 = Ks[bb];
                uint32_t b1 = Ks[bb + 4];
                mma_tf32(sf[0][nf], qf[0][k8][0], qf[0][k8][1], qf[0][k8][2], qf[0][k8][3], b0, b1);
                mma_tf32(sf[1][nf], qf[1][k8][0], qf[1][k8][1], qf[1][k8][2], qf[1][k8][3], b0, b1);
            }
        }

        // ---- causal mask on diagonal-band tiles ----
        if (kt >= ktm) {
            int off = q0 - kt * 64;
            #pragma unroll
            for (int mf = 0; mf < 2; mf++) {
                int limA = off + w * 32 + mf * 16 + gr;
                int limB = limA + 8;
                #pragma unroll
                for (int nf = 0; nf < 8; nf++) {
                    int c0 = nf * 8 + 2 * lc;
                    if (c0     > limA) sf[mf][nf][0] = -1e30f;
                    if (c0 + 1 > limA) sf[mf][nf][1] = -1e30f;
                    if (c0     > limB) sf[mf][nf][2] = -1e30f;
                    if (c0 + 1 > limB) sf[mf][nf][3] = -1e30f;
                }
            }
        }

        // ---- online softmax (base-2) ----
        #pragma unroll
        for (int mf = 0; mf < 2; mf++) {
            float tA = -1e30f, tB = -1e30f;
            #pragma unroll
            for (int nf = 0; nf < 8; nf++) {
                tA = fmaxf(tA, fmaxf(sf[mf][nf][0], sf[mf][nf][1]));
                tB = fmaxf(tB, fmaxf(sf[mf][nf][2], sf[mf][nf][3]));
            }
            tA = fmaxf(tA, __shfl_xor_sync(0xffffffffu, tA, 1));
            tA = fmaxf(tA, __shfl_xor_sync(0xffffffffu, tA, 2));
            tB = fmaxf(tB, __shfl_xor_sync(0xffffffffu, tB, 1));
            tB = fmaxf(tB, __shfl_xor_sync(0xffffffffu, tB, 2));
            float mnA = fmaxf(mx[mf][0], tA);
            float mnB = fmaxf(mx[mf][1], tB);
            float cA = ex2(mx[mf][0] - mnA);
            float cB = ex2(mx[mf][1] - mnB);
            float sumA = 0.f, sumB = 0.f;
            #pragma unroll
            for (int nf = 0; nf < 8; nf++) {
                sf[mf][nf][0] = ex2(sf[mf][nf][0] - mnA);
                sf[mf][nf][1] = ex2(sf[mf][nf][1] - mnA);
                sf[mf][nf][2] = ex2(sf[mf][nf][2] - mnB);
                sf[mf][nf][3] = ex2(sf[mf][nf][3] - mnB);
                sumA += sf[mf][nf][0] + sf[mf][nf][1];
                sumB += sf[mf][nf][2] + sf[mf][nf][3];
            }
            sumA += __shfl_xor_sync(0xffffffffu, sumA, 1);
            sumA += __shfl_xor_sync(0xffffffffu, sumA, 2);
            sumB += __shfl_xor_sync(0xffffffffu, sumB, 1);
            sumB += __shfl_xor_sync(0xffffffffu, sumB, 2);
            ls[mf][0] = ls[mf][0] * cA + sumA;  mx[mf][0] = mnA;
            ls[mf][1] = ls[mf][1] * cB + sumB;  mx[mf][1] = mnB;
            #pragma unroll
            for (int nf = 0; nf < 8; nf++) {
                oacc[mf][nf][0] *= cA; oacc[mf][nf][1] *= cA;
                oacc[mf][nf][2] *= cB; oacc[mf][nf][3] *= cB;
            }
            // store P (tf32 bits) in A-operand layout
            int rowA = (w * 32 + mf * 16 + gr) * 68;
            int rowB = rowA + 8 * 68;
            #pragma unroll
            for (int nf = 0; nf < 8; nf++) {
                int c0 = nf * 8 + 2 * lc;
                uint2 pa, pb;
                pa.x = f2tf32(sf[mf][nf][0]); pa.y = f2tf32(sf[mf][nf][1]);
                pb.x = f2tf32(sf[mf][nf][2]); pb.y = f2tf32(sf[mf][nf][3]);
                *(uint2*)&sP[rowA + c0] = pa;
                *(uint2*)&sP[rowB + c0] = pb;
            }
        }
        __syncthreads();                       // (B) P visible; K reads done

        // ---- O += P V ----
        #pragma unroll
        for (int k8 = 0; k8 < 8; k8++) {
            uint32_t pa[2][4];
            #pragma unroll
            for (int mf = 0; mf < 2; mf++) {
                int ab = (w * 32 + mf * 16 + gr) * 68 + k8 * 8 + lc;
                pa[mf][0] = sP[ab];
                pa[mf][1] = sP[ab + 8 * 68];
                pa[mf][2] = sP[ab + 4];
                pa[mf][3] = sP[ab + 8 * 68 + 4];
            }
            #pragma unroll
            for (int nf = 0; nf < 8; nf++) {
                int bb = (k8 * 8 + lc) * 68 + nf * 8 + gr;
                uint32_t b0 = Vs[bb];
                uint32_t b1 = Vs[bb + 4 * 68];
                mma_tf32(oacc[0][nf], pa[0][0], pa[0][1], pa[0][2], pa[0][3], b0, b1);
                mma_tf32(oacc[1][nf], pa[1][0], pa[1][1], pa[1][2], pa[1][3], b0, b1);
            }
        }
    }

    // ---- epilogue ----
    #pragma unroll
    for (int mf = 0; mf < 2; mf++) {
        const float iA = 1.f / ls[mf][0];
        const float iB = 1.f / ls[mf][1];
        const int rA = q0 + w * 32 + mf * 16 + gr;
        const int rB = rA + 8;
        float* oA = out + ((size_t)b * S_LEN + rA) * (NH * HDIM) + h * HDIM;
        float* oB = out + ((size_t)b * S_LEN + rB) * (NH * HDIM) + h * HDIM;
        #pragma unroll
        for (int nf = 0; nf < 8; nf++) {
            int e0 = nf * 8 + 2 * lc;
            *(float2*)(oA + e0) = make_float2(oacc[mf][nf][0] * iA, oacc[mf][nf][1] * iA);
            *(float2*)(oB + e0) = make_float2(oacc[mf][nf][2] * iB, oacc[mf][nf][3] * iB);
        }
    }
}

// ---------------------------------------------------------------------------
extern "C" void kernel_launch(void* const* d_in, const int* in_sizes, int n_in,
                              void* d_out, int out_size)
{
    const float* query = (const float*)d_in[0];
    const float* key   = (const float*)d_in[1];
    const float* value = (const float*)d_in[2];
    // d_in[3] = mask: deterministically tril -> causal logic used instead
    const float* Wq = (const float*)d_in[4];
    const float* bq = (const float*)d_in[5];
    const float* Wk = (const float*)d_in[6];
    const float* bk = (const float*)d_in[7];
    const float* Wv = (const float*)d_in[8];
    const float* bv = (const float*)d_in[9];
    float* out = (float*)d_out;

    float *pQ, *pK, *pV;
    cudaGetSymbolAddress((void**)&pQ, g_Q);
    cudaGetSymbolAddress((void**)&pK, g_K);
    cudaGetSymbolAddress((void**)&pV, g_V);

    cudaFuncSetAttribute(proj_all_kernel, cudaFuncAttributeMaxDynamicSharedMemorySize, SMEM_PROJ_BYTES);
    cudaFuncSetAttribute(attn_kernel,     cudaFuncAttributeMaxDynamicSharedMemorySize, SMEM_ATTN_BYTES);

    dim3 gp(24, (NB * S_LEN) / 256);
    proj_all_kernel<<<gp, 256, SMEM_PROJ_BYTES>>>(
        query, key, value, Wq, bq, pQ, Wk, bk, pK, Wv, bv, pV);

    dim3 ga(S_LEN / 128, NB * NH);
    attn_kernel<<<ga, 128, SMEM_ATTN_BYTES>>>(out);
}